// round 6
// baseline (speedup 1.0000x reference)
#include <cuda_runtime.h>
#include <cuda_bf16.h>
#include <cstdint>

#define N_NODES 50000
#define N_EDGES 800000
#define D_IN 128
#define N_HEADS 8
#define PER_HEAD 16
#define LEAKY_ALPHA 0.2f

// ---------------- static device scratch (no allocations allowed) ------------
__device__ float g_q[(size_t)N_NODES * 128];         // 25.6 MB
__device__ float g_k[(size_t)N_NODES * 128];         // 25.6 MB
__device__ int   g_count[N_NODES];                   // in-degree histogram
__device__ int   g_offset[N_NODES + 1];              // CSR row offsets
__device__ int   g_cursor[N_NODES];                  // scatter cursors
__device__ int   g_src_sorted[N_EDGES];              // src node per CSR slot

__device__ __forceinline__ float lrelu(float v) {
    return v > 0.0f ? v : LEAKY_ALPHA * v;
}

// ---------------- Kernel 1: Q/K fused GEMM, 8x8 register blocking ------------
// Block: 128 threads, tile 128 nodes x 64 cols. Thread (colg = t&7, ng = t>>3)
// computes 8 nodes (ng + j*16) x 8 cols (colg*8..+7). smem bytes per FMA
// halves vs the 4x4 version (the 48.5% fma cap was the smem crossbar).
// xs rows padded to 136 floats: keeps float4 alignment and puts warp-adjacent
// node rows (stride 544B = 32 mod 128) on distinct bank groups.
#define GEMM_BLOCK 128
#define TILE_N 128
#define TILE_C 64
#define XS_STRIDE 136

__global__ void __launch_bounds__(GEMM_BLOCK, 2)
qk_gemm_kernel(const float* __restrict__ x,
               const float* __restrict__ wq, const float* __restrict__ bq,
               const float* __restrict__ wk, const float* __restrict__ bk) {
    extern __shared__ float smem[];
    float* ws = smem;                        // [128][64]  = 8192 floats (32KB)
    float* xs = smem + 8192;                 // [128][136] = 17408 floats (68KB)
    float* bs = smem + 8192 + 17408;         // 64 floats

    const int t = threadIdx.x;
    const int col0 = blockIdx.y * TILE_C;    // 0,64,128,192
    const bool is_q = (col0 < 128);
    const float* wsrc = is_q ? wq : wk;
    const float* bsrc = is_q ? bq : bk;
    const int wcol0 = is_q ? col0 : (col0 - 128);

    // load weight chunk W[d][wcol0+c]
    for (int i = t; i < 128 * TILE_C; i += GEMM_BLOCK) {
        int d = i >> 6, c = i & 63;
        ws[i] = wsrc[d * 128 + wcol0 + c];
    }
    if (t < TILE_C) bs[t] = bsrc[wcol0 + t];

    // load x tile (coalesced along d), zero-fill past N_NODES
    const int n_base = blockIdx.x * TILE_N;
    for (int i = t; i < TILE_N * 32; i += GEMM_BLOCK) {
        int n = i >> 5, dc = i & 31;
        int gn = n_base + n;
        float4 v = make_float4(0.f, 0.f, 0.f, 0.f);
        if (gn < N_NODES) v = *(const float4*)(x + (size_t)gn * 128 + dc * 4);
        *(float4*)(xs + n * XS_STRIDE + dc * 4) = v;
    }
    __syncthreads();

    const int colg = t & 7;
    const int ng = t >> 3;            // 0..15; thread's nodes: ng + j*16
    const int c0 = colg * 8;

    float acc[8][8];
#pragma unroll
    for (int j = 0; j < 8; j++)
#pragma unroll
        for (int c = 0; c < 8; c++) acc[j][c] = 0.f;

    for (int d = 0; d < 128; d += 4) {
        float4 xv[8];
#pragma unroll
        for (int j = 0; j < 8; j++)
            xv[j] = *(const float4*)(xs + (ng + j * 16) * XS_STRIDE + d);
#pragma unroll
        for (int dd = 0; dd < 4; dd++) {
            float4 wa = *(const float4*)(ws + (d + dd) * TILE_C + c0);
            float4 wb = *(const float4*)(ws + (d + dd) * TILE_C + c0 + 4);
            const float* wf = (const float*)&wa;
            const float* wg = (const float*)&wb;
#pragma unroll
            for (int j = 0; j < 8; j++) {
                const float xvv = ((const float*)&xv[j])[dd];
#pragma unroll
                for (int c = 0; c < 4; c++) {
                    acc[j][c]     += xvv * wf[c];
                    acc[j][c + 4] += xvv * wg[c];
                }
            }
        }
    }

    float* gout = is_q ? g_q : g_k;
#pragma unroll
    for (int j = 0; j < 8; j++) {
        const int node = n_base + ng + j * 16;
        if (node < N_NODES) {
            float4 o0, o1;
            o0.x = acc[j][0] + bs[c0 + 0]; o0.y = acc[j][1] + bs[c0 + 1];
            o0.z = acc[j][2] + bs[c0 + 2]; o0.w = acc[j][3] + bs[c0 + 3];
            o1.x = acc[j][4] + bs[c0 + 4]; o1.y = acc[j][5] + bs[c0 + 5];
            o1.z = acc[j][6] + bs[c0 + 6]; o1.w = acc[j][7] + bs[c0 + 7];
            *(float4*)(gout + (size_t)node * 128 + wcol0 + c0) = o0;
            *(float4*)(gout + (size_t)node * 128 + wcol0 + c0 + 4) = o1;
        }
    }
}

// ---------------- CSR build: histogram -> scan -> scatter --------------------
__global__ void hist_kernel(const int* __restrict__ etgt) {
    int i = blockIdx.x * blockDim.x + threadIdx.x;
    if (i < N_EDGES) atomicAdd(&g_count[etgt[i]], 1);
}

#define SCAN_THREADS 1024
__global__ void scan_kernel() {
    __shared__ int partial[SCAN_THREADS];
    const int t = threadIdx.x;
    const int CHUNK = (N_NODES + SCAN_THREADS - 1) / SCAN_THREADS;  // 49
    const int base = t * CHUNK;

    int s = 0;
    for (int i = 0; i < CHUNK; i++) {
        int idx = base + i;
        if (idx < N_NODES) s += g_count[idx];
    }
    partial[t] = s;
    __syncthreads();

    for (int off = 1; off < SCAN_THREADS; off <<= 1) {
        int u = (t >= off) ? partial[t - off] : 0;
        __syncthreads();
        partial[t] += u;
        __syncthreads();
    }

    int run = partial[t] - s;
    for (int i = 0; i < CHUNK; i++) {
        int idx = base + i;
        if (idx < N_NODES) {
            g_offset[idx] = run;
            g_cursor[idx] = run;
            run += g_count[idx];
        }
    }
    if (t == SCAN_THREADS - 1) g_offset[N_NODES] = partial[SCAN_THREADS - 1];
}

__global__ void scatter_kernel(const int* __restrict__ esrc,
                               const int* __restrict__ etgt) {
    int i = blockIdx.x * blockDim.x + threadIdx.x;
    if (i < N_EDGES) {
        int pos = atomicAdd(&g_cursor[etgt[i]], 1);
        g_src_sorted[pos] = esrc[i];
    }
}

// ---------------- Kernel 2: per-node gather, 4-deep MLP ----------------------
// One warp per target node. All four k-row loads of an unroll group are issued
// before any dependent math, quadrupling memory-level parallelism vs R5.
__global__ void __launch_bounds__(256)
gather_kernel(const float* __restrict__ attn, float* __restrict__ out) {
    __shared__ float a_s[128];
    if (threadIdx.x < 128) a_s[threadIdx.x] = attn[threadIdx.x];
    __syncthreads();

    const int node = (blockIdx.x * blockDim.x + threadIdx.x) >> 5;
    if (node >= N_NODES) return;
    const int lane = threadIdx.x & 31;
    const int part = lane & 3;
    const int h = lane >> 2;

    const float a0 = a_s[(part * 4 + 0) * 8 + h];
    const float a1 = a_s[(part * 4 + 1) * 8 + h];
    const float a2 = a_s[(part * 4 + 2) * 8 + h];
    const float a3 = a_s[(part * 4 + 3) * 8 + h];

    const float4 qv = *(const float4*)(g_q + (size_t)node * 128 + lane * 4);

    const int start = g_offset[node];
    const int end = g_offset[node + 1];

    float4 acc = make_float4(0.f, 0.f, 0.f, 0.f);
    float dsum = 0.f;

    for (int b = start; b < end; b += 32) {
        const int cnt = min(32, end - b);
        const int src_l = (lane < cnt) ? g_src_sorted[b + lane] : 0;

        int j = 0;
        for (; j + 4 <= cnt; j += 4) {
            // broadcast 4 src indices, then issue all 4 row loads (MLP=4)
            const int s0 = __shfl_sync(0xffffffffu, src_l, j);
            const int s1 = __shfl_sync(0xffffffffu, src_l, j + 1);
            const int s2 = __shfl_sync(0xffffffffu, src_l, j + 2);
            const int s3 = __shfl_sync(0xffffffffu, src_l, j + 3);
            const float4 k0 = *(const float4*)(g_k + (size_t)s0 * 128 + lane * 4);
            const float4 k1 = *(const float4*)(g_k + (size_t)s1 * 128 + lane * 4);
            const float4 k2 = *(const float4*)(g_k + (size_t)s2 * 128 + lane * 4);
            const float4 k3 = *(const float4*)(g_k + (size_t)s3 * 128 + lane * 4);

            float p0 = lrelu(qv.x + k0.x) * a0 + lrelu(qv.y + k0.y) * a1 +
                       lrelu(qv.z + k0.z) * a2 + lrelu(qv.w + k0.w) * a3;
            float p1 = lrelu(qv.x + k1.x) * a0 + lrelu(qv.y + k1.y) * a1 +
                       lrelu(qv.z + k1.z) * a2 + lrelu(qv.w + k1.w) * a3;
            float p2 = lrelu(qv.x + k2.x) * a0 + lrelu(qv.y + k2.y) * a1 +
                       lrelu(qv.z + k2.z) * a2 + lrelu(qv.w + k2.w) * a3;
            float p3 = lrelu(qv.x + k3.x) * a0 + lrelu(qv.y + k3.y) * a1 +
                       lrelu(qv.z + k3.z) * a2 + lrelu(qv.w + k3.w) * a3;

            p0 += __shfl_xor_sync(0xffffffffu, p0, 1);
            p1 += __shfl_xor_sync(0xffffffffu, p1, 1);
            p2 += __shfl_xor_sync(0xffffffffu, p2, 1);
            p3 += __shfl_xor_sync(0xffffffffu, p3, 1);
            p0 += __shfl_xor_sync(0xffffffffu, p0, 2);
            p1 += __shfl_xor_sync(0xffffffffu, p1, 2);
            p2 += __shfl_xor_sync(0xffffffffu, p2, 2);
            p3 += __shfl_xor_sync(0xffffffffu, p3, 2);

            const float u0 = __expf(p0);
            const float u1 = __expf(p1);
            const float u2 = __expf(p2);
            const float u3 = __expf(p3);

            acc.x += u0 * k0.x + u1 * k1.x + u2 * k2.x + u3 * k3.x;
            acc.y += u0 * k0.y + u1 * k1.y + u2 * k2.y + u3 * k3.y;
            acc.z += u0 * k0.z + u1 * k1.z + u2 * k2.z + u3 * k3.z;
            acc.w += u0 * k0.w + u1 * k1.w + u2 * k2.w + u3 * k3.w;
            dsum += (u0 + u1) + (u2 + u3);
        }
        for (; j < cnt; j++) {
            const int s0 = __shfl_sync(0xffffffffu, src_l, j);
            const float4 k0 = *(const float4*)(g_k + (size_t)s0 * 128 + lane * 4);
            float p0 = lrelu(qv.x + k0.x) * a0 + lrelu(qv.y + k0.y) * a1 +
                       lrelu(qv.z + k0.z) * a2 + lrelu(qv.w + k0.w) * a3;
            p0 += __shfl_xor_sync(0xffffffffu, p0, 1);
            p0 += __shfl_xor_sync(0xffffffffu, p0, 2);
            const float u0 = __expf(p0);
            acc.x += u0 * k0.x;
            acc.y += u0 * k0.y;
            acc.z += u0 * k0.z;
            acc.w += u0 * k0.w;
            dsum += u0;
        }
    }

    const float inv = (dsum > 0.f) ? 1.f / dsum : 0.f;
    float4 o;
    o.x = fmaxf(acc.x * inv, 0.f);
    o.y = fmaxf(acc.y * inv, 0.f);
    o.z = fmaxf(acc.z * inv, 0.f);
    o.w = fmaxf(acc.w * inv, 0.f);
    *(float4*)(out + (size_t)node * 128 + lane * 4) = o;
}

// ---------------- launch ------------------------------------------------------
extern "C" void kernel_launch(void* const* d_in, const int* in_sizes, int n_in,
                              void* d_out, int out_size) {
    const float* x    = (const float*)d_in[0];
    const float* wq   = (const float*)d_in[1];
    const float* bq   = (const float*)d_in[2];
    const float* wk   = (const float*)d_in[3];
    const float* bk   = (const float*)d_in[4];
    const float* attn = (const float*)d_in[5];
    const int*   esrc = (const int*)d_in[6];
    const int*   etgt = (const int*)d_in[7];
    float* out = (float*)d_out;

    // zero the degree histogram (symbol address query, no alloc)
    void* count_ptr = nullptr;
    cudaGetSymbolAddress(&count_ptr, g_count);
    cudaMemsetAsync(count_ptr, 0, N_NODES * sizeof(int), 0);

    // CSR build
    hist_kernel<<<(N_EDGES + 255) / 256, 256>>>(etgt);
    scan_kernel<<<1, SCAN_THREADS>>>();
    scatter_kernel<<<(N_EDGES + 255) / 256, 256>>>(esrc, etgt);

    // 8x8-blocked Q/K GEMM: ~100.3KB smem, 2 CTAs/SM
    static const size_t gemm_smem = (8192 + 17408 + 64) * sizeof(float);
    cudaFuncSetAttribute(qk_gemm_kernel, cudaFuncAttributeMaxDynamicSharedMemorySize,
                         (int)gemm_smem);
    dim3 gemm_grid((N_NODES + TILE_N - 1) / TILE_N, 4);
    qk_gemm_kernel<<<gemm_grid, GEMM_BLOCK, gemm_smem>>>(x, wq, bq, wk, bk);

    // per-node gather: one warp per node, 8 nodes per 256-thread block
    gather_kernel<<<(N_NODES * 32 + 255) / 256, 256>>>(attn, out);
}

// round 7
// speedup vs baseline: 1.0285x; 1.0285x over previous
#include <cuda_runtime.h>
#include <cuda_bf16.h>
#include <cstdint>

#define N_NODES 50000
#define N_EDGES 800000
#define D_IN 128
#define N_HEADS 8
#define PER_HEAD 16
#define LEAKY_ALPHA 0.2f

// ---------------- static device scratch (no allocations allowed) ------------
__device__ float g_q[(size_t)N_NODES * 128];         // 25.6 MB
__device__ float g_k[(size_t)N_NODES * 128];         // 25.6 MB
__device__ int   g_count[N_NODES];                   // in-degree histogram
__device__ int   g_offset[N_NODES + 1];              // CSR row offsets
__device__ int   g_cursor[N_NODES];                  // scatter cursors
__device__ int   g_src_sorted[N_EDGES];              // src node per CSR slot

__device__ __forceinline__ float lrelu(float v) {
    return v > 0.0f ? v : LEAKY_ALPHA * v;
}

// ---------------- Kernel 1: Q/K fused GEMM (R5 config: 4x4, 3 CTAs/SM) ------
#define GEMM_BLOCK 256
#define NODES_PER_ITER 64
#define COLS_PER_CHUNK 64

__global__ void __launch_bounds__(GEMM_BLOCK, 3)
qk_gemm_kernel(const float* __restrict__ x,
               const float* __restrict__ wq, const float* __restrict__ bq,
               const float* __restrict__ wk, const float* __restrict__ bk) {
    extern __shared__ float smem[];
    float* ws = smem;                   // 128 * 64 floats (32KB)
    float* xs = smem + 8192;            // 64 * 128 floats (32KB)
    float* bs = smem + 16384;           // 64 floats

    const int t = threadIdx.x;
    const int col0 = blockIdx.y * COLS_PER_CHUNK;  // 0,64,128,192
    const bool is_q = (col0 < 128);
    const float* wsrc = is_q ? wq : wk;
    const float* bsrc = is_q ? bq : bk;
    const int wcol0 = is_q ? col0 : (col0 - 128);

    for (int i = t; i < 128 * COLS_PER_CHUNK; i += GEMM_BLOCK) {
        int d = i >> 6, c = i & 63;
        ws[d * COLS_PER_CHUNK + c] = wsrc[d * 128 + wcol0 + c];
    }
    if (t < COLS_PER_CHUNK) bs[t] = bsrc[wcol0 + t];
    __syncthreads();

    const int cg = t & 15;
    const int nq = t >> 4;
    const int col = cg * 4;
    const float4 bias = *(const float4*)(bs + col);

    float* gout = is_q ? g_q : g_k;
    const int gcol = wcol0 + col;

    for (int n0 = blockIdx.x * NODES_PER_ITER; n0 < N_NODES; n0 += gridDim.x * NODES_PER_ITER) {
        const int ntile = min(NODES_PER_ITER, N_NODES - n0);
        __syncthreads();
        for (int i = t; i < ntile * 32; i += GEMM_BLOCK) {
            int r = i >> 5, c4 = i & 31;
            *(float4*)(xs + r * 128 + c4 * 4) =
                *(const float4*)(x + (size_t)(n0 + r) * 128 + c4 * 4);
        }
        __syncthreads();

        float4 acc[4];
#pragma unroll
        for (int j = 0; j < 4; j++) acc[j] = bias;

#pragma unroll 4
        for (int d = 0; d < 128; d += 4) {
            float4 w0 = *(const float4*)(ws + (d + 0) * COLS_PER_CHUNK + col);
            float4 w1 = *(const float4*)(ws + (d + 1) * COLS_PER_CHUNK + col);
            float4 w2 = *(const float4*)(ws + (d + 2) * COLS_PER_CHUNK + col);
            float4 w3 = *(const float4*)(ws + (d + 3) * COLS_PER_CHUNK + col);
#pragma unroll
            for (int j = 0; j < 4; j++) {
                float4 xv = *(const float4*)(xs + (nq * 4 + j) * 128 + d);
                acc[j].x += xv.x * w0.x + xv.y * w1.x + xv.z * w2.x + xv.w * w3.x;
                acc[j].y += xv.x * w0.y + xv.y * w1.y + xv.z * w2.y + xv.w * w3.y;
                acc[j].z += xv.x * w0.z + xv.y * w1.z + xv.z * w2.z + xv.w * w3.z;
                acc[j].w += xv.x * w0.w + xv.y * w1.w + xv.z * w2.w + xv.w * w3.w;
            }
        }

#pragma unroll
        for (int j = 0; j < 4; j++) {
            const int node = n0 + nq * 4 + j;
            if (node < N_NODES)
                *(float4*)(gout + (size_t)node * 128 + gcol) = acc[j];
        }
    }
}

// ---------------- CSR build: histogram -> scan -> scatter --------------------
__global__ void hist_kernel(const int* __restrict__ etgt) {
    int i = blockIdx.x * blockDim.x + threadIdx.x;
    if (i < N_EDGES) atomicAdd(&g_count[etgt[i]], 1);
}

#define SCAN_THREADS 1024
__global__ void scan_kernel() {
    __shared__ int partial[SCAN_THREADS];
    const int t = threadIdx.x;
    const int CHUNK = (N_NODES + SCAN_THREADS - 1) / SCAN_THREADS;  // 49
    const int base = t * CHUNK;

    int s = 0;
    for (int i = 0; i < CHUNK; i++) {
        int idx = base + i;
        if (idx < N_NODES) s += g_count[idx];
    }
    partial[t] = s;
    __syncthreads();

    for (int off = 1; off < SCAN_THREADS; off <<= 1) {
        int u = (t >= off) ? partial[t - off] : 0;
        __syncthreads();
        partial[t] += u;
        __syncthreads();
    }

    int run = partial[t] - s;
    for (int i = 0; i < CHUNK; i++) {
        int idx = base + i;
        if (idx < N_NODES) {
            g_offset[idx] = run;
            g_cursor[idx] = run;
            run += g_count[idx];
        }
    }
    if (t == SCAN_THREADS - 1) g_offset[N_NODES] = partial[SCAN_THREADS - 1];
}

__global__ void scatter_kernel(const int* __restrict__ esrc,
                               const int* __restrict__ etgt) {
    int i = blockIdx.x * blockDim.x + threadIdx.x;
    if (i < N_EDGES) {
        int pos = atomicAdd(&g_cursor[etgt[i]], 1);
        g_src_sorted[pos] = esrc[i];
    }
}

// ---------------- Kernel 2: per-node gather, 2 edges per warp ----------------
// One warp per target node; the warp is split into two 16-lane groups, each
// handling one edge. Lane sl = lane&15 covers cols sl*8..sl*8+7 (2 float4).
// Head h = sl>>1; the pair (2h, 2h+1) covers head h's 16 cols; one
// shfl_xor(1) completes the head logit for BOTH edges at once. All shfl /
// expf / loop-control warp-instructions now serve 2 edges.
__global__ void __launch_bounds__(256)
gather_kernel(const float* __restrict__ attn, float* __restrict__ out) {
    __shared__ float a_s[128];
    if (threadIdx.x < 128) a_s[threadIdx.x] = attn[threadIdx.x];
    __syncthreads();

    const int node = (blockIdx.x * blockDim.x + threadIdx.x) >> 5;
    if (node >= N_NODES) return;
    const int lane = threadIdx.x & 31;
    const int half = lane >> 4;        // 0 or 1: which edge of the pair
    const int sl = lane & 15;
    const int h = sl >> 1;
    const int c0 = sl * 8;             // global col base for this lane

    // attn weights for this lane's 8 cols: c_local = (sl&1)*8 + j
    float aw[8];
#pragma unroll
    for (int j = 0; j < 8; j++)
        aw[j] = a_s[((sl & 1) * 8 + j) * 8 + h];

    const float4 qv0 = *(const float4*)(g_q + (size_t)node * 128 + c0);
    const float4 qv1 = *(const float4*)(g_q + (size_t)node * 128 + c0 + 4);

    const int start = g_offset[node];
    const int end = g_offset[node + 1];

    float4 acc0 = make_float4(0.f, 0.f, 0.f, 0.f);
    float4 acc1 = make_float4(0.f, 0.f, 0.f, 0.f);
    float dsum = 0.f;

    for (int b = start; b < end; b += 32) {
        const int cnt = min(32, end - b);
        const int src_l = (lane < cnt) ? g_src_sorted[b + lane] : 0;

        for (int j = 0; j < cnt; j += 4) {
            // pair A = edges j, j+1 ; pair B = edges j+2, j+3
            const int iA = j + half;
            const int iB = j + 2 + half;
            const int sA = __shfl_sync(0xffffffffu, src_l, iA & 31);
            const int sB = __shfl_sync(0xffffffffu, src_l, iB & 31);

            // issue all 4 row-chunk loads (MLP=4 per lane)
            const float4 kA0 = *(const float4*)(g_k + (size_t)sA * 128 + c0);
            const float4 kA1 = *(const float4*)(g_k + (size_t)sA * 128 + c0 + 4);
            const float4 kB0 = *(const float4*)(g_k + (size_t)sB * 128 + c0);
            const float4 kB1 = *(const float4*)(g_k + (size_t)sB * 128 + c0 + 4);

            float pA = lrelu(qv0.x + kA0.x) * aw[0] + lrelu(qv0.y + kA0.y) * aw[1] +
                       lrelu(qv0.z + kA0.z) * aw[2] + lrelu(qv0.w + kA0.w) * aw[3] +
                       lrelu(qv1.x + kA1.x) * aw[4] + lrelu(qv1.y + kA1.y) * aw[5] +
                       lrelu(qv1.z + kA1.z) * aw[6] + lrelu(qv1.w + kA1.w) * aw[7];
            float pB = lrelu(qv0.x + kB0.x) * aw[0] + lrelu(qv0.y + kB0.y) * aw[1] +
                       lrelu(qv0.z + kB0.z) * aw[2] + lrelu(qv0.w + kB0.w) * aw[3] +
                       lrelu(qv1.x + kB1.x) * aw[4] + lrelu(qv1.y + kB1.y) * aw[5] +
                       lrelu(qv1.z + kB1.z) * aw[6] + lrelu(qv1.w + kB1.w) * aw[7];

            pA += __shfl_xor_sync(0xffffffffu, pA, 1);  // head logit (both lanes)
            pB += __shfl_xor_sync(0xffffffffu, pB, 1);

            const float uA = (iA < cnt) ? __expf(pA) : 0.f;
            const float uB = (iB < cnt) ? __expf(pB) : 0.f;

            acc0.x += uA * kA0.x + uB * kB0.x;
            acc0.y += uA * kA0.y + uB * kB0.y;
            acc0.z += uA * kA0.z + uB * kB0.z;
            acc0.w += uA * kA0.w + uB * kB0.w;
            acc1.x += uA * kA1.x + uB * kB1.x;
            acc1.y += uA * kA1.y + uB * kB1.y;
            acc1.z += uA * kA1.z + uB * kB1.z;
            acc1.w += uA * kA1.w + uB * kB1.w;
            dsum += uA + uB;
        }
    }

    // combine the two 16-lane halves (same cols, different edges)
    acc0.x += __shfl_xor_sync(0xffffffffu, acc0.x, 16);
    acc0.y += __shfl_xor_sync(0xffffffffu, acc0.y, 16);
    acc0.z += __shfl_xor_sync(0xffffffffu, acc0.z, 16);
    acc0.w += __shfl_xor_sync(0xffffffffu, acc0.w, 16);
    acc1.x += __shfl_xor_sync(0xffffffffu, acc1.x, 16);
    acc1.y += __shfl_xor_sync(0xffffffffu, acc1.y, 16);
    acc1.z += __shfl_xor_sync(0xffffffffu, acc1.z, 16);
    acc1.w += __shfl_xor_sync(0xffffffffu, acc1.w, 16);
    dsum += __shfl_xor_sync(0xffffffffu, dsum, 16);

    if (half == 0) {
        const float inv = (dsum > 0.f) ? 1.f / dsum : 0.f;
        float4 o0, o1;
        o0.x = fmaxf(acc0.x * inv, 0.f); o0.y = fmaxf(acc0.y * inv, 0.f);
        o0.z = fmaxf(acc0.z * inv, 0.f); o0.w = fmaxf(acc0.w * inv, 0.f);
        o1.x = fmaxf(acc1.x * inv, 0.f); o1.y = fmaxf(acc1.y * inv, 0.f);
        o1.z = fmaxf(acc1.z * inv, 0.f); o1.w = fmaxf(acc1.w * inv, 0.f);
        *(float4*)(out + (size_t)node * 128 + c0) = o0;
        *(float4*)(out + (size_t)node * 128 + c0 + 4) = o1;
    }
}

// ---------------- launch ------------------------------------------------------
extern "C" void kernel_launch(void* const* d_in, const int* in_sizes, int n_in,
                              void* d_out, int out_size) {
    const float* x    = (const float*)d_in[0];
    const float* wq   = (const float*)d_in[1];
    const float* bq   = (const float*)d_in[2];
    const float* wk   = (const float*)d_in[3];
    const float* bk   = (const float*)d_in[4];
    const float* attn = (const float*)d_in[5];
    const int*   esrc = (const int*)d_in[6];
    const int*   etgt = (const int*)d_in[7];
    float* out = (float*)d_out;

    // zero the degree histogram (symbol address query, no alloc)
    void* count_ptr = nullptr;
    cudaGetSymbolAddress(&count_ptr, g_count);
    cudaMemsetAsync(count_ptr, 0, N_NODES * sizeof(int), 0);

    // CSR build
    hist_kernel<<<(N_EDGES + 255) / 256, 256>>>(etgt);
    scan_kernel<<<1, SCAN_THREADS>>>();
    scatter_kernel<<<(N_EDGES + 255) / 256, 256>>>(esrc, etgt);

    // 4x4-blocked Q/K GEMM: ~64.25KB smem, 3 CTAs/SM (R5 config)
    static const size_t gemm_smem = (8192 + 8192 + 64) * sizeof(float);
    cudaFuncSetAttribute(qk_gemm_kernel, cudaFuncAttributeMaxDynamicSharedMemorySize,
                         (int)gemm_smem);
    dim3 gemm_grid(148, 4);
    qk_gemm_kernel<<<gemm_grid, GEMM_BLOCK, gemm_smem>>>(x, wq, bq, wk, bk);

    // per-node gather: one warp per node, 8 nodes per 256-thread block
    gather_kernel<<<(N_NODES * 32 + 255) / 256, 256>>>(attn, out);
}